// round 4
// baseline (speedup 1.0000x reference)
#include <cuda_runtime.h>

// DCN cross, B=8192, D=256, L=4 — algebraic collapse:
//   x_l = a_l * x0 + v_l,  v_l row-independent (sum of biases),
//   a_{l+1} = a_l*(1 + d_l) + c_l,  d_l = x0.W_l,  c_l = v_l.W_l.
// One parallel reduction phase (4 dots on x0) instead of 4 serial ones.

constexpr int D = 256;
constexpr int L = 4;
constexpr int R = 2;   // rows per warp

__device__ __forceinline__ float dot8(const float4& a0, const float4& a1,
                                      const float4& b0, const float4& b1) {
    float t = a0.x * b0.x;
    t = fmaf(a0.y, b0.y, t);
    t = fmaf(a0.z, b0.z, t);
    t = fmaf(a0.w, b0.w, t);
    t = fmaf(a1.x, b1.x, t);
    t = fmaf(a1.y, b1.y, t);
    t = fmaf(a1.z, b1.z, t);
    t = fmaf(a1.w, b1.w, t);
    return t;
}

__global__ __launch_bounds__(256)
void cross_kernel(const float* __restrict__ x,
                  const float* __restrict__ W,
                  const float* __restrict__ b_lin,
                  const float* __restrict__ bias,
                  float* __restrict__ out,
                  int B)
{
    const int warp_id = (blockIdx.x * blockDim.x + threadIdx.x) >> 5;
    const int lane    = threadIdx.x & 31;
    const int row0    = warp_id * R;
    if (row0 >= B) return;

    // x0 rows: lane owns elems [4*lane..4*lane+3] and [128+4*lane..+3]
    float4 xa[R], xb[R];
    #pragma unroll
    for (int r = 0; r < R; ++r) {
        const float4* xrow = reinterpret_cast<const float4*>(x + (size_t)(row0 + r) * D);
        xa[r] = xrow[lane];
        xb[r] = xrow[lane + 32];
    }

    // v accumulator (v_0 = 0); pc = partial c_l; pd = partial d_{r,l}
    float4 va = make_float4(0.f, 0.f, 0.f, 0.f);
    float4 vb = make_float4(0.f, 0.f, 0.f, 0.f);
    float red[(R + 1) * L];   // [r*L + l] = pd, last L = pc

    #pragma unroll
    for (int l = 0; l < L; ++l) {
        const float4* Wr = reinterpret_cast<const float4*>(W + l * D);
        const float4 w0 = Wr[lane];
        const float4 w1 = Wr[lane + 32];

        red[R * L + l] = dot8(va, vb, w0, w1);          // partial c_l = v_l . W_l
        #pragma unroll
        for (int r = 0; r < R; ++r)
            red[r * L + l] = dot8(xa[r], xb[r], w0, w1); // partial d_{r,l} = x0 . W_l

        // v_{l+1} = v_l + b_lin_l + bias_l   (L2-resident, tiny)
        const float4* Br = reinterpret_cast<const float4*>(bias + l * D);
        const float4 b0 = Br[lane];
        const float4 b1 = Br[lane + 32];
        const float bl = b_lin[l];
        va.x += bl + b0.x;  va.y += bl + b0.y;  va.z += bl + b0.z;  va.w += bl + b0.w;
        vb.x += bl + b1.x;  vb.y += bl + b1.y;  vb.z += bl + b1.z;  vb.w += bl + b1.w;
    }

    // Single reduction phase: (R+1)*L independent butterfly ladders, pipelined.
    #pragma unroll
    for (int o = 16; o > 0; o >>= 1) {
        #pragma unroll
        for (int k = 0; k < (R + 1) * L; ++k)
            red[k] += __shfl_xor_sync(0xffffffffu, red[k], o);
    }

    // Scalar recurrence per row (trivial serial chain: ~8 FLOPs)
    #pragma unroll
    for (int r = 0; r < R; ++r) {
        float a = 1.0f;
        #pragma unroll
        for (int l = 0; l < L; ++l)
            a = fmaf(a, red[r * L + l], a + red[R * L + l]);  // a += a*d_l + c_l

        float4 oa, ob;
        oa.x = fmaf(a, xa[r].x, va.x);
        oa.y = fmaf(a, xa[r].y, va.y);
        oa.z = fmaf(a, xa[r].z, va.z);
        oa.w = fmaf(a, xa[r].w, va.w);
        ob.x = fmaf(a, xb[r].x, vb.x);
        ob.y = fmaf(a, xb[r].y, vb.y);
        ob.z = fmaf(a, xb[r].z, vb.z);
        ob.w = fmaf(a, xb[r].w, vb.w);

        float4* orow = reinterpret_cast<float4*>(out + (size_t)(row0 + r) * D);
        orow[lane]      = oa;
        orow[lane + 32] = ob;
    }
}

extern "C" void kernel_launch(void* const* d_in, const int* in_sizes, int n_in,
                              void* d_out, int out_size)
{
    const float* x     = (const float*)d_in[0];
    const float* W     = (const float*)d_in[1];
    const float* b_lin = (const float*)d_in[2];
    const float* bias  = (const float*)d_in[3];
    float* out         = (float*)d_out;

    const int B = in_sizes[0] / D;                 // 8192
    const int threads = 256;                       // 8 warps/block
    const int rows_per_block = (threads / 32) * R; // 16 rows/block
    const int blocks = (B + rows_per_block - 1) / rows_per_block;  // 512

    cross_kernel<<<blocks, threads>>>(x, W, b_lin, bias, out, B);
}